// round 13
// baseline (speedup 1.0000x reference)
#include <cuda_runtime.h>
#include <cuda_bf16.h>
#include <math.h>

#define NN 4096
#define EE 16384
#define PHID 64
#define EPSF 1e-8f

// Q = round(B/scale_r) int8 (16MB, L2-resident); per-row c = scale_r/d_r.
__device__ char g_Q[(size_t)NN * NN];
__device__ float g_c[NN];

// ---------------------------------------------------------------------------
// k_prep (R11, measured ~88% of HBM peak): 2 rows per CTA in registers;
// f_mean in registers; fused reductions; int8 quantize with per-row scale.
// ---------------------------------------------------------------------------
__global__ __launch_bounds__(256) void k_prep(const float* __restrict__ A,
                                              const float* __restrict__ f0,
                                              const float* __restrict__ f1) {
    __shared__ float rsum[2][8];
    __shared__ float rmax[2][8];
    __shared__ float s_cinv[2];
    int tid = threadIdx.x;
    int wid = tid >> 5, lane = tid & 31;

    float4 f[4];
#pragma unroll
    for (int it = 0; it < 4; ++it) {
        int q = tid + it * 256;
        float4 a = ((const float4*)f0)[q];
        float4 b = ((const float4*)f1)[q];
        f[it].x = 0.5f * (a.x + b.x);
        f[it].y = 0.5f * (a.y + b.y);
        f[it].z = 0.5f * (a.z + b.z);
        f[it].w = 0.5f * (a.w + b.w);
    }

    float4 m[2][4];
    float acc[2], vmax[2];
#pragma unroll
    for (int r = 0; r < 2; ++r) {
        int row = blockIdx.x * 2 + r;
        const float4* a4 = (const float4*)(A + (size_t)row * NN);
        acc[r] = 0.f;
        vmax[r] = 0.f;
#pragma unroll
        for (int it = 0; it < 4; ++it) {
            float4 v = a4[tid + it * 256];
            m[r][it].x = v.x * f[it].x;
            m[r][it].y = v.y * f[it].y;
            m[r][it].z = v.z * f[it].z;
            m[r][it].w = v.w * f[it].w;
            float e0 = m[r][it].x + EPSF, e1 = m[r][it].y + EPSF;
            float e2 = m[r][it].z + EPSF, e3 = m[r][it].w + EPSF;
            acc[r] += e0 * e0 + e1 * e1 + e2 * e2 + e3 * e3;
            vmax[r] = fmaxf(vmax[r],
                            fmaxf(fmaxf(fabsf(m[r][it].x), fabsf(m[r][it].y)),
                                  fmaxf(fabsf(m[r][it].z), fabsf(m[r][it].w))));
        }
    }
#pragma unroll
    for (int off = 16; off; off >>= 1) {
#pragma unroll
        for (int r = 0; r < 2; ++r) {
            acc[r] += __shfl_xor_sync(0xffffffffu, acc[r], off);
            vmax[r] = fmaxf(vmax[r], __shfl_xor_sync(0xffffffffu, vmax[r], off));
        }
    }
    if (lane == 0) {
#pragma unroll
        for (int r = 0; r < 2; ++r) {
            rsum[r][wid] = acc[r];
            rmax[r][wid] = vmax[r];
        }
    }
    __syncthreads();
    if (tid < 2) {
        float t = 0.f, mx = 0.f;
#pragma unroll
        for (int w = 0; w < 8; w++) {
            t += rsum[tid][w];
            mx = fmaxf(mx, rmax[tid][w]);
        }
        float scale = fmaxf(mx, 1e-20f) * (1.0f / 127.0f);
        g_c[blockIdx.x * 2 + tid] = scale / sqrtf(t);
        s_cinv[tid] = 1.0f / scale;
    }
    __syncthreads();

#pragma unroll
    for (int r = 0; r < 2; ++r) {
        float inv_scale = s_cinv[r];
        uchar4 pk[4];
#pragma unroll
        for (int it = 0; it < 4; ++it) {
            int q0 = __float2int_rn(m[r][it].x * inv_scale);
            int q1 = __float2int_rn(m[r][it].y * inv_scale);
            int q2 = __float2int_rn(m[r][it].z * inv_scale);
            int q3 = __float2int_rn(m[r][it].w * inv_scale);
            pk[it].x = (unsigned char)(char)max(-127, min(127, q0));
            pk[it].y = (unsigned char)(char)max(-127, min(127, q1));
            pk[it].z = (unsigned char)(char)max(-127, min(127, q2));
            pk[it].w = (unsigned char)(char)max(-127, min(127, q3));
        }
        uint4 o;
        o.x = *(unsigned*)&pk[0];
        o.y = *(unsigned*)&pk[1];
        o.z = *(unsigned*)&pk[2];
        o.w = *(unsigned*)&pk[3];
        // fixed column permutation: dot/norm-invariant (both rows of an edge
        // share the same packing)
        ((uint4*)(g_Q + (size_t)(blockIdx.x * 2 + r) * NN))[tid] = o;
    }
}

// ---------------------------------------------------------------------------
// k_edge: one warp per edge, LEAN body, __launch_bounds__(256, 8) to force
// regs <= 32 -> 2048 threads/SM (64 warps) -- the latency-bound fix.
// ---------------------------------------------------------------------------
__global__ __launch_bounds__(256, 8) void k_edge(
    const int* __restrict__ src0, const int* __restrict__ dst0,
    const int* __restrict__ src1, const int* __restrict__ dst1,
    const float* __restrict__ p1w1, const float* __restrict__ p1b1,
    const float* __restrict__ p1w2, const float* __restrict__ p1b2,
    const float* __restrict__ p2w1, const float* __restrict__ p2b1,
    const float* __restrict__ p2w2, const float* __restrict__ p2b2,
    float* __restrict__ out) {
    int gw = (int)((blockIdx.x * blockDim.x + threadIdx.x) >> 5);
    int lane = threadIdx.x & 31;
    int layer = gw >> 14;  // / EE
    int e = gw & (EE - 1);
    int s = layer ? __ldg(src1 + e) : __ldg(src0 + e);
    int t = layer ? __ldg(dst1 + e) : __ldg(dst0 + e);

    const uint4* ps = (const uint4*)(g_Q + (size_t)s * NN) + lane;
    const uint4* pt = (const uint4*)(g_Q + (size_t)t * NN) + lane;

    int acc0 = 0, acc1 = 0, acc2 = 0, acc3 = 0;
#pragma unroll
    for (int k = 0; k < 8; k++) {
        uint4 a = ps[k * 32];
        uint4 b = pt[k * 32];
        acc0 = __dp4a((int)a.x, (int)b.x, acc0);
        acc1 = __dp4a((int)a.y, (int)b.y, acc1);
        acc2 = __dp4a((int)a.z, (int)b.z, acc2);
        acc3 = __dp4a((int)a.w, (int)b.w, acc3);
    }
    int acc = (acc0 + acc1) + (acc2 + acc3);
    acc = __reduce_add_sync(0xffffffffu, acc);

    float x = (float)acc * g_c[s] * g_c[t];

    int o = layer * PHID;
    // MLP 1: 1 -> 64 -> 1 (2 hidden units per lane)
    float h0 = fmaxf(fmaf(x, p1w1[o + lane], p1b1[o + lane]), 0.f);
    float h1 = fmaxf(fmaf(x, p1w1[o + lane + 32], p1b1[o + lane + 32]), 0.f);
    float y = fmaf(h0, p1w2[o + lane], h1 * p1w2[o + lane + 32]);
#pragma unroll
    for (int off = 16; off; off >>= 1)
        y += __shfl_xor_sync(0xffffffffu, y, off);
    y += p1b2[layer];
    float x2 = 0.5f * y;  // BETA * y / LM

    // MLP 2
    float g0 = fmaxf(fmaf(x2, p2w1[o + lane], p2b1[o + lane]), 0.f);
    float g1 = fmaxf(fmaf(x2, p2w1[o + lane + 32], p2b1[o + lane + 32]), 0.f);
    float z = fmaf(g0, p2w2[o + lane], g1 * p2w2[o + lane + 32]);
#pragma unroll
    for (int off = 16; off; off >>= 1)
        z += __shfl_xor_sync(0xffffffffu, z, off);
    z += p2b2[layer];

    if (lane == 0) out[gw] = z;
}

extern "C" void kernel_launch(void* const* d_in, const int* in_sizes, int n_in,
                              void* d_out, int out_size) {
    const float* A    = (const float*)d_in[0];
    const int* src0   = (const int*)d_in[1];
    const int* dst0   = (const int*)d_in[2];
    const int* src1   = (const int*)d_in[3];
    const int* dst1   = (const int*)d_in[4];
    const float* f0   = (const float*)d_in[5];
    const float* f1   = (const float*)d_in[6];
    const float* p1w1 = (const float*)d_in[7];
    const float* p1b1 = (const float*)d_in[8];
    const float* p1w2 = (const float*)d_in[9];
    const float* p1b2 = (const float*)d_in[10];
    const float* p2w1 = (const float*)d_in[11];
    const float* p2b1 = (const float*)d_in[12];
    const float* p2w2 = (const float*)d_in[13];
    const float* p2b2 = (const float*)d_in[14];
    float* out = (float*)d_out;

    k_prep<<<NN / 2, 256>>>(A, f0, f1);
    // 32768 warps, 8 warps per 256-thread CTA -> 4096 CTAs
    k_edge<<<4096, 256>>>(src0, dst0, src1, dst1,
                          p1w1, p1b1, p1w2, p1b2,
                          p2w1, p2b1, p2w2, p2b2, out);
}